// round 12
// baseline (speedup 1.0000x reference)
#include <cuda_runtime.h>
#include <cstdint>

// R12: final probe — T=512 (same 64 warps/SM via launch_bounds(512,4), half
// the CTAs of R11). Kernel is at the DRAM-mix roofline (86.5% / ~6.85TB/s,
// confirmed across R8-R11 occupancy & unroll sweep); this targets only
// block-dispatch/wave-tail overhead.

// Problem constants (fixed shapes from reference)
static constexpr long long N  = 100000;   // nodes
static constexpr long long E  = 3200000;  // edges
static constexpr long long D  = 256;      // node feat
static constexpr long long De = 32;       // edge feat
static constexpr long long B  = 128;      // graphs

// Region chunk counts, float4 (16B) units. All boundaries are %4==0 floats.
// Order: 0:x copy 1:x zero 2:ei_r0 3:heads 4:ei_r1 5:tails 6:ea copy 7:ea zero 8:batch 9:arangeB
static constexpr unsigned C0 = (unsigned)(N * D / 4);    //  6,400,000
static constexpr unsigned C1 = (unsigned)(B * D / 4);    //      8,192
static constexpr unsigned C2 = (unsigned)(E / 4);        //    800,000
static constexpr unsigned C3 = (unsigned)(N / 4);        //     25,000
static constexpr unsigned C4 = C2;
static constexpr unsigned C5 = C3;
static constexpr unsigned C6 = (unsigned)(E * De / 4);   // 25,600,000
static constexpr unsigned C7 = (unsigned)(N * De / 4);   //    800,000
static constexpr unsigned C8 = C3;
static constexpr unsigned C9 = (unsigned)(B / 4);        //         32

// Output bases (prefix sums, float4 units) — all < 2^32
static constexpr unsigned O0 = 0;
static constexpr unsigned O1 = O0 + C0;
static constexpr unsigned O2 = O1 + C1;
static constexpr unsigned O3 = O2 + C2;
static constexpr unsigned O4 = O3 + C3;
static constexpr unsigned O5 = O4 + C4;
static constexpr unsigned O6 = O5 + C5;
static constexpr unsigned O7 = O6 + C6;
static constexpr unsigned O8 = O7 + C7;
static constexpr unsigned O9 = O8 + C8;

static constexpr int T = 512;
static constexpr int UNROLL = 4;
static constexpr unsigned CPB = T * UNROLL;  // 2048 chunks per block

static constexpr unsigned cdivu(unsigned a, unsigned b) { return (a + b - 1) / b; }
static constexpr unsigned B0 = cdivu(C0, CPB);
static constexpr unsigned B1 = cdivu(C1, CPB);
static constexpr unsigned B2 = cdivu(C2, CPB);
static constexpr unsigned B3 = cdivu(C3, CPB);
static constexpr unsigned B4 = cdivu(C4, CPB);
static constexpr unsigned B5 = cdivu(C5, CPB);
static constexpr unsigned B6 = cdivu(C6, CPB);
static constexpr unsigned B7 = cdivu(C7, CPB);
static constexpr unsigned B8 = cdivu(C8, CPB);
static constexpr unsigned B9 = cdivu(C9, CPB);
static constexpr unsigned P1 = B0;
static constexpr unsigned P2 = P1 + B1;
static constexpr unsigned P3 = P2 + B2;
static constexpr unsigned P4 = P3 + B3;
static constexpr unsigned P5 = P4 + B4;
static constexpr unsigned P6 = P5 + B5;
static constexpr unsigned P7 = P6 + B6;
static constexpr unsigned P8 = P7 + B7;
static constexpr unsigned P9 = P8 + B8;
static constexpr unsigned P_END = P9 + B9;

// Branch-free region bodies. c0 = region-local first chunk for this thread.
// nlim = min(region chunk count, remaining d_out capacity) — single guard.

__device__ __forceinline__ void do_copy(
    const float4* __restrict__ src, float4* __restrict__ dst,
    unsigned c0, unsigned nlim)
{
    unsigned c[UNROLL]; bool ok[UNROLL]; float4 v[UNROLL];
#pragma unroll
    for (int k = 0; k < UNROLL; k++) { c[k] = c0 + k * T; ok[k] = c[k] < nlim; }
#pragma unroll
    for (int k = 0; k < UNROLL; k++) if (ok[k]) v[k] = __ldcs(src + c[k]);
#pragma unroll
    for (int k = 0; k < UNROLL; k++) if (ok[k]) __stcs(dst + c[k], v[k]);
}

__device__ __forceinline__ void do_zero(
    float4* __restrict__ dst, unsigned c0, unsigned nlim)
{
    const float4 z = make_float4(0.f, 0.f, 0.f, 0.f);
#pragma unroll
    for (int k = 0; k < UNROLL; k++) {
        unsigned c = c0 + k * T;
        if (c < nlim) __stcs(dst + c, z);
    }
}

__device__ __forceinline__ void do_cvt(
    const int4* __restrict__ src, float4* __restrict__ dst,
    unsigned c0, unsigned nlim, int bias)
{
    unsigned c[UNROLL]; bool ok[UNROLL]; int4 a[UNROLL];
#pragma unroll
    for (int k = 0; k < UNROLL; k++) { c[k] = c0 + k * T; ok[k] = c[k] < nlim; }
#pragma unroll
    for (int k = 0; k < UNROLL; k++) if (ok[k]) a[k] = __ldcs(src + c[k]);
#pragma unroll
    for (int k = 0; k < UNROLL; k++) if (ok[k]) {
        float4 v = make_float4((float)(a[k].x + bias), (float)(a[k].y + bias),
                               (float)(a[k].z + bias), (float)(a[k].w + bias));
        __stcs(dst + c[k], v);
    }
}

__device__ __forceinline__ void do_arange(
    float4* __restrict__ dst, unsigned c0, unsigned nlim)
{
#pragma unroll
    for (int k = 0; k < UNROLL; k++) {
        unsigned c = c0 + k * T;
        if (c < nlim) {
            float f = (float)(4u * c);
            __stcs(dst + c, make_float4(f, f + 1.f, f + 2.f, f + 3.f));
        }
    }
}

__device__ __forceinline__ unsigned minu(unsigned a, unsigned b) { return a < b ? a : b; }

__global__ void __launch_bounds__(T, 4) vnode_fused_kernel(
    const float* __restrict__ x, const int* __restrict__ ei,
    const float* __restrict__ ea, const int* __restrict__ batch,
    float* __restrict__ out, unsigned lim4)
{
    const unsigned b = blockIdx.x;
    float4* o4 = (float4*)out;

    // Scalar region dispatch (constants fold to immediates); big regions first.
    if (b >= P6 && b < P7) {          // ea copy — 74% of blocks
        unsigned c0 = (b - P6) * CPB + threadIdx.x;
        do_copy((const float4*)ea, o4 + O6, c0, minu(C6, lim4 - O6));
    } else if (b < P1) {              // x copy — 19%
        unsigned c0 = b * CPB + threadIdx.x;
        do_copy((const float4*)x, o4 + O0, c0, minu(C0, lim4 - O0));
    } else if (b < P2) {              // x virtual-node zeros
        unsigned c0 = (b - P1) * CPB + threadIdx.x;
        do_zero(o4 + O1, c0, minu(C1, lim4 - O1));
    } else if (b < P3) {              // ei row 0 cvt
        unsigned c0 = (b - P2) * CPB + threadIdx.x;
        do_cvt((const int4*)ei, o4 + O2, c0, minu(C2, lim4 - O2), 0);
    } else if (b < P4) {              // heads = arange(N)
        unsigned c0 = (b - P3) * CPB + threadIdx.x;
        do_arange(o4 + O3, c0, minu(C3, lim4 - O3));
    } else if (b < P5) {              // ei row 1 cvt
        unsigned c0 = (b - P4) * CPB + threadIdx.x;
        do_cvt((const int4*)(ei + E), o4 + O4, c0, minu(C4, lim4 - O4), 0);
    } else if (b < P6) {              // tails = N + batch
        unsigned c0 = (b - P5) * CPB + threadIdx.x;
        do_cvt((const int4*)batch, o4 + O5, c0, minu(C5, lim4 - O5), (int)N);
    } else if (b < P8) {              // ea virtual-edge zeros
        unsigned c0 = (b - P7) * CPB + threadIdx.x;
        do_zero(o4 + O7, c0, minu(C7, lim4 - O7));
    } else if (b < P9) {              // new_batch head = batch cast
        unsigned c0 = (b - P8) * CPB + threadIdx.x;
        do_cvt((const int4*)batch, o4 + O8, c0, minu(C8, lim4 - O8), 0);
    } else {                          // arange(B)
        unsigned c0 = (b - P9) * CPB + threadIdx.x;
        do_arange(o4 + O9, c0, minu(C9, lim4 - O9));
    }
}

extern "C" void kernel_launch(void* const* d_in, const int* in_sizes, int n_in,
                              void* d_out, int out_size) {
    const float* x     = (const float*)d_in[0];
    const int*   ei    = (const int*)d_in[1];
    const float* ea    = (const float*)d_in[2];
    const int*   batch = (const int*)d_in[3];
    float* out = (float*)d_out;

    unsigned lim4 = (unsigned)(out_size / 4);  // whole float4s in d_out
    vnode_fused_kernel<<<P_END, T>>>(x, ei, ea, batch, out, lim4);
}

// round 13
// speedup vs baseline: 1.0042x; 1.0042x over previous
#include <cuda_runtime.h>
#include <cstdint>

// FINAL (converged): fused single-kernel concat/convert with block-range
// region dispatch. T=256, UNROLL=4, launch_bounds(256,8): regs=31, occ~82%,
// kernel 150.5-150.7us @ 86.4-86.6% DRAM (~6.85 TB/s). R8-R12 sweep over
// block size {256,512}, warps/SM {40-64}, per-thread MLP {4,8} all plateau
// at 150.5-152.3us — HBM controller roofline for this 50/50 R/W mix.
// Mandatory traffic 1.09 GB (each input byte read once, each output byte
// written once); no further reduction possible.

// Problem constants (fixed shapes from reference)
static constexpr long long N  = 100000;   // nodes
static constexpr long long E  = 3200000;  // edges
static constexpr long long D  = 256;      // node feat
static constexpr long long De = 32;       // edge feat
static constexpr long long B  = 128;      // graphs

// Region chunk counts, float4 (16B) units. All boundaries are %4==0 floats.
// Order: 0:x copy 1:x zero 2:ei_r0 3:heads 4:ei_r1 5:tails 6:ea copy 7:ea zero 8:batch 9:arangeB
static constexpr unsigned C0 = (unsigned)(N * D / 4);    //  6,400,000
static constexpr unsigned C1 = (unsigned)(B * D / 4);    //      8,192
static constexpr unsigned C2 = (unsigned)(E / 4);        //    800,000
static constexpr unsigned C3 = (unsigned)(N / 4);        //     25,000
static constexpr unsigned C4 = C2;
static constexpr unsigned C5 = C3;
static constexpr unsigned C6 = (unsigned)(E * De / 4);   // 25,600,000
static constexpr unsigned C7 = (unsigned)(N * De / 4);   //    800,000
static constexpr unsigned C8 = C3;
static constexpr unsigned C9 = (unsigned)(B / 4);        //         32

// Output bases (prefix sums, float4 units) — all < 2^32
static constexpr unsigned O0 = 0;
static constexpr unsigned O1 = O0 + C0;
static constexpr unsigned O2 = O1 + C1;
static constexpr unsigned O3 = O2 + C2;
static constexpr unsigned O4 = O3 + C3;
static constexpr unsigned O5 = O4 + C4;
static constexpr unsigned O6 = O5 + C5;
static constexpr unsigned O7 = O6 + C6;
static constexpr unsigned O8 = O7 + C7;
static constexpr unsigned O9 = O8 + C8;

static constexpr int T = 256;
static constexpr int UNROLL = 4;
static constexpr unsigned CPB = T * UNROLL;  // 1024 chunks per block

static constexpr unsigned cdivu(unsigned a, unsigned b) { return (a + b - 1) / b; }
static constexpr unsigned B0 = cdivu(C0, CPB);
static constexpr unsigned B1 = cdivu(C1, CPB);
static constexpr unsigned B2 = cdivu(C2, CPB);
static constexpr unsigned B3 = cdivu(C3, CPB);
static constexpr unsigned B4 = cdivu(C4, CPB);
static constexpr unsigned B5 = cdivu(C5, CPB);
static constexpr unsigned B6 = cdivu(C6, CPB);
static constexpr unsigned B7 = cdivu(C7, CPB);
static constexpr unsigned B8 = cdivu(C8, CPB);
static constexpr unsigned B9 = cdivu(C9, CPB);
static constexpr unsigned P1 = B0;
static constexpr unsigned P2 = P1 + B1;
static constexpr unsigned P3 = P2 + B2;
static constexpr unsigned P4 = P3 + B3;
static constexpr unsigned P5 = P4 + B4;
static constexpr unsigned P6 = P5 + B5;
static constexpr unsigned P7 = P6 + B6;
static constexpr unsigned P8 = P7 + B7;
static constexpr unsigned P9 = P8 + B8;
static constexpr unsigned P_END = P9 + B9;

// Branch-free region bodies. c0 = region-local first chunk for this thread.
// nlim = min(region chunk count, remaining d_out capacity) — single guard.

__device__ __forceinline__ void do_copy(
    const float4* __restrict__ src, float4* __restrict__ dst,
    unsigned c0, unsigned nlim)
{
    unsigned c[UNROLL]; bool ok[UNROLL]; float4 v[UNROLL];
#pragma unroll
    for (int k = 0; k < UNROLL; k++) { c[k] = c0 + k * T; ok[k] = c[k] < nlim; }
#pragma unroll
    for (int k = 0; k < UNROLL; k++) if (ok[k]) v[k] = __ldcs(src + c[k]);
#pragma unroll
    for (int k = 0; k < UNROLL; k++) if (ok[k]) __stcs(dst + c[k], v[k]);
}

__device__ __forceinline__ void do_zero(
    float4* __restrict__ dst, unsigned c0, unsigned nlim)
{
    const float4 z = make_float4(0.f, 0.f, 0.f, 0.f);
#pragma unroll
    for (int k = 0; k < UNROLL; k++) {
        unsigned c = c0 + k * T;
        if (c < nlim) __stcs(dst + c, z);
    }
}

__device__ __forceinline__ void do_cvt(
    const int4* __restrict__ src, float4* __restrict__ dst,
    unsigned c0, unsigned nlim, int bias)
{
    unsigned c[UNROLL]; bool ok[UNROLL]; int4 a[UNROLL];
#pragma unroll
    for (int k = 0; k < UNROLL; k++) { c[k] = c0 + k * T; ok[k] = c[k] < nlim; }
#pragma unroll
    for (int k = 0; k < UNROLL; k++) if (ok[k]) a[k] = __ldcs(src + c[k]);
#pragma unroll
    for (int k = 0; k < UNROLL; k++) if (ok[k]) {
        float4 v = make_float4((float)(a[k].x + bias), (float)(a[k].y + bias),
                               (float)(a[k].z + bias), (float)(a[k].w + bias));
        __stcs(dst + c[k], v);
    }
}

__device__ __forceinline__ void do_arange(
    float4* __restrict__ dst, unsigned c0, unsigned nlim)
{
#pragma unroll
    for (int k = 0; k < UNROLL; k++) {
        unsigned c = c0 + k * T;
        if (c < nlim) {
            float f = (float)(4u * c);
            __stcs(dst + c, make_float4(f, f + 1.f, f + 2.f, f + 3.f));
        }
    }
}

__device__ __forceinline__ unsigned minu(unsigned a, unsigned b) { return a < b ? a : b; }

__global__ void __launch_bounds__(T, 8) vnode_fused_kernel(
    const float* __restrict__ x, const int* __restrict__ ei,
    const float* __restrict__ ea, const int* __restrict__ batch,
    float* __restrict__ out, unsigned lim4)
{
    const unsigned b = blockIdx.x;
    float4* o4 = (float4*)out;

    // Scalar region dispatch (constants fold to immediates); big regions first.
    if (b >= P6 && b < P7) {          // ea copy — 74% of blocks
        unsigned c0 = (b - P6) * CPB + threadIdx.x;
        do_copy((const float4*)ea, o4 + O6, c0, minu(C6, lim4 - O6));
    } else if (b < P1) {              // x copy — 19%
        unsigned c0 = b * CPB + threadIdx.x;
        do_copy((const float4*)x, o4 + O0, c0, minu(C0, lim4 - O0));
    } else if (b < P2) {              // x virtual-node zeros
        unsigned c0 = (b - P1) * CPB + threadIdx.x;
        do_zero(o4 + O1, c0, minu(C1, lim4 - O1));
    } else if (b < P3) {              // ei row 0 cvt
        unsigned c0 = (b - P2) * CPB + threadIdx.x;
        do_cvt((const int4*)ei, o4 + O2, c0, minu(C2, lim4 - O2), 0);
    } else if (b < P4) {              // heads = arange(N)
        unsigned c0 = (b - P3) * CPB + threadIdx.x;
        do_arange(o4 + O3, c0, minu(C3, lim4 - O3));
    } else if (b < P5) {              // ei row 1 cvt
        unsigned c0 = (b - P4) * CPB + threadIdx.x;
        do_cvt((const int4*)(ei + E), o4 + O4, c0, minu(C4, lim4 - O4), 0);
    } else if (b < P6) {              // tails = N + batch
        unsigned c0 = (b - P5) * CPB + threadIdx.x;
        do_cvt((const int4*)batch, o4 + O5, c0, minu(C5, lim4 - O5), (int)N);
    } else if (b < P8) {              // ea virtual-edge zeros
        unsigned c0 = (b - P7) * CPB + threadIdx.x;
        do_zero(o4 + O7, c0, minu(C7, lim4 - O7));
    } else if (b < P9) {              // new_batch head = batch cast
        unsigned c0 = (b - P8) * CPB + threadIdx.x;
        do_cvt((const int4*)batch, o4 + O8, c0, minu(C8, lim4 - O8), 0);
    } else {                          // arange(B)
        unsigned c0 = (b - P9) * CPB + threadIdx.x;
        do_arange(o4 + O9, c0, minu(C9, lim4 - O9));
    }
}

extern "C" void kernel_launch(void* const* d_in, const int* in_sizes, int n_in,
                              void* d_out, int out_size) {
    const float* x     = (const float*)d_in[0];
    const int*   ei    = (const int*)d_in[1];
    const float* ea    = (const float*)d_in[2];
    const int*   batch = (const int*)d_in[3];
    float* out = (float*)d_out;

    unsigned lim4 = (unsigned)(out_size / 4);  // whole float4s in d_out
    vnode_fused_kernel<<<P_END, T>>>(x, ei, ea, batch, out, lim4);
}